// round 4
// baseline (speedup 1.0000x reference)
#include <cuda_runtime.h>
#include <math.h>

#define B   16
#define Hh  128
#define Ww  128
#define CI  64
#define CO  64
#define MD  16
#define THETA 0.04908738521234052f   // 2*pi/128

typedef unsigned long long u64;

__device__ __forceinline__ u64 pk(float lo, float hi) {
    u64 r; asm("mov.b64 %0, {%1,%2};" : "=l"(r) : "f"(lo), "f"(hi)); return r;
}
__device__ __forceinline__ void upk(u64 v, float& lo, float& hi) {
    asm("mov.b64 {%0,%1}, %2;" : "=f"(lo), "=f"(hi) : "l"(v));
}
__device__ __forceinline__ u64 fma2(u64 a, u64 b, u64 c) {
    u64 d; asm("fma.rn.f32x2 %0, %1, %2, %3;" : "=l"(d) : "l"(a), "l"(b), "l"(c)); return d;
}
__device__ __forceinline__ u64 add2(u64 a, u64 b) {
    u64 d; asm("add.rn.f32x2 %0, %1, %2;" : "=l"(d) : "l"(a), "l"(b)); return d;
}

#define SGN2 0x8000000080000000ULL

// ---- scratch (device globals; allocation-free). 16B aligned for vector access ----
static __device__ __align__(16) float  g_Ax[B*MD*Hh*CI];     // [b][kx][h][i]  8 MB
static __device__ __align__(16) float  g_Ay[B*MD*Hh*CI];     //                8 MB
static __device__ __align__(16) float  g_Xx[MD*MD*B*CI];     // [m][b][i]      1 MB
static __device__ __align__(16) float  g_Xy[MD*MD*B*CI];     //                1 MB
static __device__ __align__(16) u64    g_W1[MD*MD*CI*CO];    // [m][i*64+o] (wr,wi)  8 MB
static __device__ __align__(16) float2 g_O [B*MD*MD*CO];     // [b][kx][ky][o]       2 MB
static __device__ __align__(16) float  g_Gx[B*Hh*MD*CO];     // [b][h][kx][o]  8 MB
static __device__ __align__(16) float  g_Gy[B*Hh*MD*CO];     //                8 MB
// twiddle tables [k][phase] packed
static __device__ __align__(16) u64    g_Tcc[MD*128];        // (c,c)
static __device__ __align__(16) u64    g_Tss[MD*128];        // (s,s)
static __device__ __align__(16) u64    g_TEc[MD*128];        // E: (2Sc,2Sc), k=0 -> (S,S)
static __device__ __align__(16) u64    g_TEs[MD*128];        // E: (-2Ss,-2Ss), k=0 -> 0

// ============ stage T: weight pack [m][i*64+o] + twiddle tables ============
__global__ void __launch_bounds__(256) stageT(const float* __restrict__ wr,
                                              const float* __restrict__ wi) {
    int tid = threadIdx.x;
    if (blockIdx.x >= 1024) {                       // twiddle-table blocks
        int idx = (blockIdx.x - 1024) * 256 + tid;  // 0..2047
        int k = idx >> 7, ph = idx & 127;
        float s, c;
        sincosf((float)((k * ph) & 127) * THETA, &s, &c);
        g_Tcc[idx] = pk(c, c);
        g_Tss[idx] = pk(s, s);
        const float S = 1.0f / 16384.0f;
        if (k == 0) { g_TEc[idx] = pk(S, S); g_TEs[idx] = 0; }
        else {
            float fc = 2.0f * S * c, fs = -2.0f * S * s;
            g_TEc[idx] = pk(fc, fc); g_TEs[idx] = pk(fs, fs);
        }
        return;
    }
    __shared__ float sr[32][33];
    __shared__ float si[32][33];
    int bm  = blockIdx.x & 7;
    int bio = blockIdx.x >> 3;
    int tx  = tid & 31;
    int ty  = tid >> 5;
#pragma unroll
    for (int r = 0; r < 4; ++r) {
        int iol = ty + r * 8;
        size_t g = (size_t)(bio * 32 + iol) * 256 + bm * 32 + tx;
        sr[iol][tx] = wr[g];
        si[iol][tx] = wi[g];
    }
    __syncthreads();
#pragma unroll
    for (int r = 0; r < 4; ++r) {
        int ml = ty + r * 8;
        g_W1[(size_t)(bm * 32 + ml) * 4096 + bio * 32 + tx] = pk(sr[tx][ml], si[tx][ml]);
    }
}

// ============ stage A: A[b][kx][h][i] = sum_w x e^{-i kx w th}  (SoA out) ============
__global__ void __launch_bounds__(128) stageA(const float* __restrict__ x) {
    __shared__ __align__(16) float sx[64 * 64];    // 16 KB (64 w rows)
    __shared__ __align__(16) u64 sTc[MD * 128];    // 16 KB
    __shared__ __align__(16) u64 sTs[MD * 128];    // 16 KB
    int b = blockIdx.x >> 7, h = blockIdx.x & 127;
    int tid = threadIdx.x;
    for (int l = tid; l < 1024; l += 128) {
        ((float4*)sTc)[l] = ((const float4*)g_Tcc)[l];
        ((float4*)sTs)[l] = ((const float4*)g_Tss)[l];
    }
    int ip = tid & 31, kq = tid >> 5, i0 = 2 * ip;
    u64 re[4] = {0,0,0,0}, im[4] = {0,0,0,0};
    const float* xrow = x + (size_t)(b * Hh + h) * Ww * CI;
#pragma unroll
    for (int ch = 0; ch < 2; ++ch) {
        __syncthreads();
        const float4* src = (const float4*)(xrow + ch * 4096);
        for (int l = tid; l < 1024; l += 128) ((float4*)sx)[l] = src[l];
        __syncthreads();
#pragma unroll 4
        for (int wl = 0; wl < 64; ++wl) {
            int w = ch * 64 + wl;
            u64 v = *(const u64*)&sx[wl * 64 + i0];
#pragma unroll
            for (int q = 0; q < 4; ++q) {
                int kx = kq + 4 * q;
                re[q] = fma2(v, sTc[kx * 128 + w], re[q]);
                im[q] = fma2(v, sTs[kx * 128 + w], im[q]);
            }
        }
    }
#pragma unroll
    for (int q = 0; q < 4; ++q) {
        int kx = kq + 4 * q;
        size_t base = ((size_t)(b * MD + kx) * Hh + h) * CI;
        *(u64*)&g_Ax[base + i0] = re[q];
        *(u64*)&g_Ay[base + i0] = im[q] ^ SGN2;    // im = -sum v*s
    }
}

// ============ stage B: X[m][b][i] = sum_h A e^{-i ky h th} ============
__global__ void __launch_bounds__(256) stageB() {
    __shared__ __align__(16) float sAx[32 * 64];   // 8 KB
    __shared__ __align__(16) float sAy[32 * 64];   // 8 KB
    __shared__ __align__(16) u64 sTc[MD * 128];    // 16 KB
    __shared__ __align__(16) u64 sTs[MD * 128];    // 16 KB
    int b = blockIdx.x >> 4, kx = blockIdx.x & 15;
    int tid = threadIdx.x;
    for (int l = tid; l < 1024; l += 256) {
        ((float4*)sTc)[l] = ((const float4*)g_Tcc)[l];
        ((float4*)sTs)[l] = ((const float4*)g_Tss)[l];
    }
    int ip = tid & 31, kyq = tid >> 5, i0 = 2 * ip;
    int ky0 = kyq, ky1 = kyq + 8;
    u64 p0=0,q0=0,r0=0,s0=0,p1=0,q1=0,r1=0,s1=0;
    const float* Abx = g_Ax + (size_t)(b * MD + kx) * Hh * CI;
    const float* Aby = g_Ay + (size_t)(b * MD + kx) * Hh * CI;
#pragma unroll
    for (int ch = 0; ch < 4; ++ch) {
        __syncthreads();
        const float4* sx4 = (const float4*)(Abx + ch * 2048);
        const float4* sy4 = (const float4*)(Aby + ch * 2048);
        for (int l = tid; l < 512; l += 256) {
            ((float4*)sAx)[l] = sx4[l];
            ((float4*)sAy)[l] = sy4[l];
        }
        __syncthreads();
#pragma unroll 4
        for (int hl = 0; hl < 32; ++hl) {
            int h = ch * 32 + hl;
            u64 ar = *(const u64*)&sAx[hl * 64 + i0];
            u64 ai = *(const u64*)&sAy[hl * 64 + i0];
            u64 c0 = sTc[ky0 * 128 + h], t0 = sTs[ky0 * 128 + h];
            u64 c1 = sTc[ky1 * 128 + h], t1 = sTs[ky1 * 128 + h];
            p0 = fma2(ar, c0, p0);  q0 = fma2(ai, t0, q0);
            r0 = fma2(ai, c0, r0);  s0 = fma2(ar, t0, s0);
            p1 = fma2(ar, c1, p1);  q1 = fma2(ai, t1, q1);
            r1 = fma2(ai, c1, r1);  s1 = fma2(ar, t1, s1);
        }
    }
    // re = p + q ; im = r - s
    u64 xre0 = add2(p0, q0), xim0 = add2(r0, s0 ^ SGN2);
    u64 xre1 = add2(p1, q1), xim1 = add2(r1, s1 ^ SGN2);
    size_t b0 = ((size_t)(ky0 * MD + kx) * B + b) * CI;
    size_t b1 = ((size_t)(ky1 * MD + kx) * B + b) * CI;
    *(u64*)&g_Xx[b0 + i0] = xre0;  *(u64*)&g_Xy[b0 + i0] = xim0;
    *(u64*)&g_Xx[b1 + i0] = xre1;  *(u64*)&g_Xy[b1 + i0] = xim1;
}

// ============ stage C: O[b][kx][ky][o] = sum_i X[m][b][i] * W[m][i][o] ============
__global__ void __launch_bounds__(1024) stageC() {
    __shared__ __align__(16) u64 sW [CI * CO];     // 32 KB
    __shared__ __align__(16) u64 sXx[B * CI];      // 8 KB (x.x,x.x)
    __shared__ __align__(16) u64 sXy[B * CI];      // 8 KB (x.y,x.y)
    int m = blockIdx.x;
    int kx = m & 15, ky = m >> 4;
    int tid = threadIdx.x;
    const float4* Wsrc = (const float4*)(g_W1 + (size_t)m * 4096);
    for (int l = tid; l < 2048; l += 1024) ((float4*)sW)[l] = Wsrc[l];
    {
        int l = tid;
        float vx = g_Xx[m * 1024 + l], vy = g_Xy[m * 1024 + l];
        sXx[l] = pk(vx, vx);
        sXy[l] = pk(vy, vy);
    }
    __syncthreads();
    int o = tid & 63, b = tid >> 6;
    u64 accA = 0, accB = 0;     // A = sum xr*(wr,wi), B = sum xi*(wr,wi)
    const u64* xp = &sXx[b * 64];
    const u64* yp = &sXy[b * 64];
#pragma unroll 8
    for (int i = 0; i < CI; ++i) {
        u64 w1 = sW[i * 64 + o];
        accA = fma2(xp[i], w1, accA);
        accB = fma2(yp[i], w1, accB);
    }
    float alo, ahi, blo, bhi;
    upk(accA, alo, ahi); upk(accB, blo, bhi);
    // out = (alo - bhi) + i(ahi + blo)
    g_O[((size_t)(b * MD + kx) * MD + ky) * CO + o] = make_float2(alo - bhi, ahi + blo);
}

// ============ stage D: G[b][h][kx][o] = sum_ky O e^{+i ky h th}  (SoA out) ============
__global__ void __launch_bounds__(256) stageD() {
    __shared__ __align__(16) float sOx[MD * CO];   // 4 KB
    __shared__ __align__(16) float sOy[MD * CO];   // 4 KB
    __shared__ __align__(16) u64 sTc2[MD * 64];    // 8 KB  [ky][hloc]
    __shared__ __align__(16) u64 sTs2[MD * 64];    // 8 KB
    int half = blockIdx.x & 1;
    int kx   = (blockIdx.x >> 1) & 15;
    int b    = blockIdx.x >> 5;
    int hb   = half * 64;
    int tid  = threadIdx.x;
    for (int l = tid; l < 1024; l += 256) {
        int ky = l >> 6, hloc = l & 63;
        sTc2[l] = g_Tcc[ky * 128 + hb + hloc];
        sTs2[l] = g_Tss[ky * 128 + hb + hloc];
    }
    const float2* Os = &g_O[(size_t)(b * MD + kx) * MD * CO];
    for (int l = tid; l < 1024; l += 256) { float2 v = Os[l]; sOx[l] = v.x; sOy[l] = v.y; }
    __syncthreads();

    int op = tid & 31, hl = tid >> 5;
    u64 re[8] = {0,0,0,0,0,0,0,0};
    u64 im[8] = {0,0,0,0,0,0,0,0};
#pragma unroll
    for (int ky = 0; ky < MD; ++ky) {
        u64 vx = *(const u64*)&sOx[ky * 64 + op * 2];
        u64 vy = *(const u64*)&sOy[ky * 64 + op * 2];
        u64 vyn = vy ^ SGN2;
#pragma unroll
        for (int jj = 0; jj < 8; ++jj) {
            int hloc = hl * 8 + jj;
            u64 cc = sTc2[ky * 64 + hloc];
            u64 ss = sTs2[ky * 64 + hloc];
            re[jj] = fma2(vx,  cc, re[jj]);  re[jj] = fma2(vyn, ss, re[jj]);
            im[jj] = fma2(vx,  ss, im[jj]);  im[jj] = fma2(vy,  cc, im[jj]);
        }
    }
#pragma unroll
    for (int jj = 0; jj < 8; ++jj) {
        int h = hb + hl * 8 + jj;
        size_t base = ((size_t)(b * Hh + h) * MD + kx) * CO + op * 2;
        *(u64*)&g_Gx[base] = re[jj];
        *(u64*)&g_Gy[base] = im[jj];
    }
}

// ============ stage E: y = S*Gx(0) + sum_{kx>=1} 2S(Gx c - Gy s) ============
#define YPAD 66
__global__ void __launch_bounds__(128) stageE(float* __restrict__ y) {
    __shared__ __align__(16) float sGx[MD * CO];    // 4 KB
    __shared__ __align__(16) float sGy[MD * CO];    // 4 KB
    __shared__ __align__(16) float sY [Ww * YPAD];  // 33.8 KB
    int b = blockIdx.x >> 7, h = blockIdx.x & 127;
    int tid = threadIdx.x;                           // = w
    const float4* Gxs = (const float4*)&g_Gx[(size_t)(b * Hh + h) * MD * CO];
    const float4* Gys = (const float4*)&g_Gy[(size_t)(b * Hh + h) * MD * CO];
    for (int l = tid; l < MD * CO / 4; l += 128) {
        ((float4*)sGx)[l] = Gxs[l];
        ((float4*)sGy)[l] = Gys[l];
    }
    int w = tid;
    u64 tc[16], ts[16];
#pragma unroll
    for (int kx = 0; kx < MD; ++kx) {
        tc[kx] = g_TEc[kx * 128 + w];
        ts[kx] = g_TEs[kx * 128 + w];
    }
    __syncthreads();

#pragma unroll 2
    for (int oq = 0; oq < 16; ++oq) {
        u64 a01 = 0, a23 = 0;
#pragma unroll
        for (int kx = 0; kx < MD; ++kx) {
            ulonglong2 vx = *(const ulonglong2*)&sGx[kx * 64 + oq * 4];
            ulonglong2 vy = *(const ulonglong2*)&sGy[kx * 64 + oq * 4];
            a01 = fma2(vx.x, tc[kx], a01);  a01 = fma2(vy.x, ts[kx], a01);
            a23 = fma2(vx.y, tc[kx], a23);  a23 = fma2(vy.y, ts[kx], a23);
        }
        *(u64*)&sY[w * YPAD + oq * 4    ] = a01;
        *(u64*)&sY[w * YPAD + oq * 4 + 2] = a23;
    }
    __syncthreads();
    float* yb = y + (size_t)(b * Hh + h) * Ww * CO;
    for (int l = tid; l < Ww * CO / 2; l += 128) {
        int idx = l * 2;
        int ww = idx >> 6, o = idx & 63;
        *(u64*)&yb[idx] = *(const u64*)&sY[ww * YPAD + o];
    }
}

extern "C" void kernel_launch(void* const* d_in, const int* in_sizes, int n_in,
                              void* d_out, int out_size) {
    const float* x  = (const float*)d_in[0];
    const float* wr = (const float*)d_in[1];
    const float* wi = (const float*)d_in[2];
    float* y = (float*)d_out;

    stageT<<<1032, 256>>>(wr, wi);   // 1024 weight blocks + 8 table blocks
    stageA<<<B * Hh, 128>>>(x);
    stageB<<<B * MD, 256>>>();
    stageC<<<MD * MD, 1024>>>();
    stageD<<<B * MD * 2, 256>>>();
    stageE<<<B * Hh, 128>>>(y);
}

// round 6
// speedup vs baseline: 1.4236x; 1.4236x over previous
#include <cuda_runtime.h>
#include <math.h>

#define B   16
#define Hh  128
#define Ww  128
#define CI  64
#define CO  64
#define MD  16
#define THETA 0.04908738521234052f   // 2*pi/128

typedef unsigned long long u64;

__device__ __forceinline__ u64 pk(float lo, float hi) {
    u64 r; asm("mov.b64 %0, {%1,%2};" : "=l"(r) : "f"(lo), "f"(hi)); return r;
}
__device__ __forceinline__ u64 fma2(u64 a, u64 b, u64 c) {
    u64 d; asm("fma.rn.f32x2 %0, %1, %2, %3;" : "=l"(d) : "l"(a), "l"(b), "l"(c)); return d;
}
__device__ __forceinline__ u64 add2(u64 a, u64 b) {
    u64 d; asm("add.rn.f32x2 %0, %1, %2;" : "=l"(d) : "l"(a), "l"(b)); return d;
}
#define SGN2 0x8000000080000000ULL

// ---- scratch (device globals; allocation-free). 16B aligned ----
static __device__ __align__(16) float g_Ax[B*MD*Hh*CI];     // [b][kx][h][i]  8 MB
static __device__ __align__(16) float g_Ay[B*MD*Hh*CI];     //                8 MB
static __device__ __align__(16) float g_Xx[MD*MD*B*CI];     // [m][b][i]      1 MB
static __device__ __align__(16) float g_Xy[MD*MD*B*CI];     //                1 MB
static __device__ __align__(16) float g_Wr[MD*MD*CI*CO];    // [m][i*64+o]    4 MB
static __device__ __align__(16) float g_Wi[MD*MD*CI*CO];    //                4 MB
static __device__ __align__(16) float g_Ox[B*MD*MD*CO];     // [b][kx][ky][o] 1 MB
static __device__ __align__(16) float g_Oy[B*MD*MD*CO];     //                1 MB
static __device__ __align__(16) float g_Gx[B*Hh*MD*CO];     // [b][h][kx][o]  8 MB
static __device__ __align__(16) float g_Gy[B*Hh*MD*CO];     //                8 MB
// twiddle tables
static __device__ __align__(16) u64 g_Tcc[MD*128];   // (c,c)   [k][ph]
static __device__ __align__(16) u64 g_Tss[MD*128];   // (s,s)
static __device__ __align__(16) u64 g_Tbc[128];      // base row (c,c) for ph
static __device__ __align__(16) u64 g_Tbs[128];      // base row (s,s)
static __device__ __align__(16) u64 g_TEc[MD*128];   // E: k=0:(S,S) else (2Sc,2Sc)
static __device__ __align__(16) u64 g_TEs[MD*128];   // E: k=0:0    else (-2Ss,-2Ss)

// ============ stage T: weight transpose (SoA) + twiddle tables ============
__global__ void __launch_bounds__(256) stageT(const float* __restrict__ wr,
                                              const float* __restrict__ wi) {
    int tid = threadIdx.x;
    if (blockIdx.x >= 1024) {                       // twiddle-table blocks
        int idx = (blockIdx.x - 1024) * 256 + tid;  // 0..2047
        int k = idx >> 7, ph = idx & 127;
        float s, c;
        sincosf((float)((k * ph) & 127) * THETA, &s, &c);
        g_Tcc[idx] = pk(c, c);
        g_Tss[idx] = pk(s, s);
        if (k == 1) { g_Tbc[ph] = pk(c, c); g_Tbs[ph] = pk(s, s); }
        const float S = 1.0f / 16384.0f;
        if (k == 0) { g_TEc[idx] = pk(S, S); g_TEs[idx] = 0; }
        else {
            float fc = 2.0f * S * c, fs = -2.0f * S * s;
            g_TEc[idx] = pk(fc, fc); g_TEs[idx] = pk(fs, fs);
        }
        return;
    }
    __shared__ float sr[32][33];
    __shared__ float si[32][33];
    int bm  = blockIdx.x & 7;
    int bio = blockIdx.x >> 3;
    int tx  = tid & 31;
    int ty  = tid >> 5;
#pragma unroll
    for (int r = 0; r < 4; ++r) {
        int iol = ty + r * 8;
        size_t g = (size_t)(bio * 32 + iol) * 256 + bm * 32 + tx;
        sr[iol][tx] = wr[g];
        si[iol][tx] = wi[g];
    }
    __syncthreads();
#pragma unroll
    for (int r = 0; r < 4; ++r) {
        int ml = ty + r * 8;
        size_t dst = (size_t)(bm * 32 + ml) * 4096 + bio * 32 + tx;
        g_Wr[dst] = sr[tx][ml];
        g_Wi[dst] = si[tx][ml];
    }
}

// ============ stage A: A[b][kx][h][i] = sum_w x e^{-i kx w th} (4 h rows/block) ============
__global__ void __launch_bounds__(128) stageA(const float* __restrict__ x) {
    __shared__ __align__(16) float sxd[4][32 * 64];   // 32 KB (4 rows, 32-w chunk)
    __shared__ __align__(16) u64 sbc[128];            // 1 KB base (c,c)
    __shared__ __align__(16) u64 sbs[128];            // 1 KB base (s,s)
    int b  = blockIdx.x >> 5;
    int hq = blockIdx.x & 31;
    int h0 = hq * 4;
    int tid = threadIdx.x;
    if (tid < 64) {   // 128 u64 = 64 float4  (R5 bug: loaded only half)
        ((float4*)sbc)[tid] = ((const float4*)g_Tbc)[tid];
        ((float4*)sbs)[tid] = ((const float4*)g_Tbs)[tid];
    }
    int ip = tid & 31, kq = tid >> 5;   // kx = kq + 4q
    int i0 = 2 * ip;
    int kxs0 = kq, kxs1 = kq + 4, kxs2 = kq + 8, kxs3 = kq + 12;
    u64 re[4][4], im[4][4];
#pragma unroll
    for (int r = 0; r < 4; ++r)
#pragma unroll
        for (int q = 0; q < 4; ++q) { re[r][q] = 0; im[r][q] = 0; }

    for (int wc = 0; wc < 4; ++wc) {
        __syncthreads();
#pragma unroll
        for (int r = 0; r < 4; ++r) {
            const float4* src = (const float4*)(x + ((size_t)(b * Hh + h0 + r) * Ww + wc * 32) * CI);
            float4* dst = (float4*)sxd[r];
            for (int l = tid; l < 512; l += 128) dst[l] = src[l];
        }
        __syncthreads();
        int w0 = wc * 32;
        int id0 = (kxs0 * w0) & 127, id1 = (kxs1 * w0) & 127;
        int id2 = (kxs2 * w0) & 127, id3 = (kxs3 * w0) & 127;
#pragma unroll 4
        for (int wl = 0; wl < 32; ++wl) {
            u64 v0 = *(const u64*)&sxd[0][wl * 64 + i0];
            u64 v1 = *(const u64*)&sxd[1][wl * 64 + i0];
            u64 v2 = *(const u64*)&sxd[2][wl * 64 + i0];
            u64 v3 = *(const u64*)&sxd[3][wl * 64 + i0];
            u64 cc, ss;
            cc = sbc[id0]; ss = sbs[id0]; id0 = (id0 + kxs0) & 127;
            re[0][0]=fma2(v0,cc,re[0][0]); im[0][0]=fma2(v0,ss,im[0][0]);
            re[1][0]=fma2(v1,cc,re[1][0]); im[1][0]=fma2(v1,ss,im[1][0]);
            re[2][0]=fma2(v2,cc,re[2][0]); im[2][0]=fma2(v2,ss,im[2][0]);
            re[3][0]=fma2(v3,cc,re[3][0]); im[3][0]=fma2(v3,ss,im[3][0]);
            cc = sbc[id1]; ss = sbs[id1]; id1 = (id1 + kxs1) & 127;
            re[0][1]=fma2(v0,cc,re[0][1]); im[0][1]=fma2(v0,ss,im[0][1]);
            re[1][1]=fma2(v1,cc,re[1][1]); im[1][1]=fma2(v1,ss,im[1][1]);
            re[2][1]=fma2(v2,cc,re[2][1]); im[2][1]=fma2(v2,ss,im[2][1]);
            re[3][1]=fma2(v3,cc,re[3][1]); im[3][1]=fma2(v3,ss,im[3][1]);
            cc = sbc[id2]; ss = sbs[id2]; id2 = (id2 + kxs2) & 127;
            re[0][2]=fma2(v0,cc,re[0][2]); im[0][2]=fma2(v0,ss,im[0][2]);
            re[1][2]=fma2(v1,cc,re[1][2]); im[1][2]=fma2(v1,ss,im[1][2]);
            re[2][2]=fma2(v2,cc,re[2][2]); im[2][2]=fma2(v2,ss,im[2][2]);
            re[3][2]=fma2(v3,cc,re[3][2]); im[3][2]=fma2(v3,ss,im[3][2]);
            cc = sbc[id3]; ss = sbs[id3]; id3 = (id3 + kxs3) & 127;
            re[0][3]=fma2(v0,cc,re[0][3]); im[0][3]=fma2(v0,ss,im[0][3]);
            re[1][3]=fma2(v1,cc,re[1][3]); im[1][3]=fma2(v1,ss,im[1][3]);
            re[2][3]=fma2(v2,cc,re[2][3]); im[2][3]=fma2(v2,ss,im[2][3]);
            re[3][3]=fma2(v3,cc,re[3][3]); im[3][3]=fma2(v3,ss,im[3][3]);
        }
    }
#pragma unroll
    for (int q = 0; q < 4; ++q) {
        int kx = kq + 4 * q;
#pragma unroll
        for (int r = 0; r < 4; ++r) {
            size_t base = ((size_t)(b * MD + kx) * Hh + (h0 + r)) * CI;
            *(u64*)&g_Ax[base + i0] = re[r][q];
            *(u64*)&g_Ay[base + i0] = im[r][q] ^ SGN2;   // im = -sum v*s
        }
    }
}

// ============ stage B: X[m][b][i] = sum_h A e^{-i ky h th} ============
__global__ void __launch_bounds__(256) stageB() {
    __shared__ __align__(16) float sBx[64 * 64];   // 16 KB (64-h chunk)
    __shared__ __align__(16) float sBy[64 * 64];   // 16 KB
    __shared__ __align__(16) u64 sbc[128];
    __shared__ __align__(16) u64 sbs[128];
    int b = blockIdx.x >> 4, kx = blockIdx.x & 15;
    int tid = threadIdx.x;
    if (tid < 64) {   // 128 u64 = 64 float4  (R5 bug: loaded only half)
        ((float4*)sbc)[tid] = ((const float4*)g_Tbc)[tid];
        ((float4*)sbs)[tid] = ((const float4*)g_Tbs)[tid];
    }
    int ipl = tid & 15, ky = tid >> 4;
    int i0a = 2 * ipl, i0b = 2 * ipl + 32;
    u64 Pa=0,Qa=0,Ra=0,Sa=0, Pb=0,Qb=0,Rb=0,Sb=0;
    const float* Abx = g_Ax + (size_t)(b * MD + kx) * Hh * CI;
    const float* Aby = g_Ay + (size_t)(b * MD + kx) * Hh * CI;
    for (int hc = 0; hc < 2; ++hc) {
        __syncthreads();
        const float4* sx4 = (const float4*)(Abx + hc * 4096);
        const float4* sy4 = (const float4*)(Aby + hc * 4096);
        for (int l = tid; l < 1024; l += 256) {
            ((float4*)sBx)[l] = sx4[l];
            ((float4*)sBy)[l] = sy4[l];
        }
        __syncthreads();
        int idx = (ky * hc * 64) & 127;
#pragma unroll 4
        for (int hl = 0; hl < 64; ++hl) {
            u64 cc = sbc[idx], ss = sbs[idx];
            idx = (idx + ky) & 127;
            u64 ara = *(const u64*)&sBx[hl * 64 + i0a];
            u64 aia = *(const u64*)&sBy[hl * 64 + i0a];
            u64 arb = *(const u64*)&sBx[hl * 64 + i0b];
            u64 aib = *(const u64*)&sBy[hl * 64 + i0b];
            Pa = fma2(ara, cc, Pa);  Qa = fma2(aia, ss, Qa);
            Ra = fma2(aia, cc, Ra);  Sa = fma2(ara, ss, Sa);
            Pb = fma2(arb, cc, Pb);  Qb = fma2(aib, ss, Qb);
            Rb = fma2(aib, cc, Rb);  Sb = fma2(arb, ss, Sb);
        }
    }
    // re = P + Q ; im = R - S
    size_t base = ((size_t)(ky * MD + kx) * B + b) * CI;
    *(u64*)&g_Xx[base + i0a] = add2(Pa, Qa);
    *(u64*)&g_Xy[base + i0a] = add2(Ra, Sa ^ SGN2);
    *(u64*)&g_Xx[base + i0b] = add2(Pb, Qb);
    *(u64*)&g_Xy[base + i0b] = add2(Rb, Sb ^ SGN2);
}

// ============ stage C: O[b][kx][ky][o] = sum_i X[m][b][i]*W[m][i][o] (SoA out) ============
__global__ void __launch_bounds__(128) stageC() {
    __shared__ __align__(16) float sWr[CI * CO];   // 16 KB
    __shared__ __align__(16) float sWi[CI * CO];   // 16 KB
    __shared__ __align__(16) u64 sXx[B * CI];      // 8 KB ( x, x)
    __shared__ __align__(16) u64 sXn[B * CI];      // 8 KB (-y,-y)
    int m = blockIdx.x;
    int kx = m & 15, ky = m >> 4;
    int tid = threadIdx.x;
    const float4* Wr4 = (const float4*)(g_Wr + (size_t)m * 4096);
    const float4* Wi4 = (const float4*)(g_Wi + (size_t)m * 4096);
    for (int l = tid; l < 1024; l += 128) {
        ((float4*)sWr)[l] = Wr4[l];
        ((float4*)sWi)[l] = Wi4[l];
    }
    for (int l = tid; l < 1024; l += 128) {
        float vx = g_Xx[m * 1024 + l];
        float vy = g_Xy[m * 1024 + l];
        sXx[l] = pk(vx, vx);
        sXn[l] = pk(-vy, -vy);
    }
    __syncthreads();
    int op = tid & 31, bq = tid >> 5;   // b = bq + 4j
    u64 P[4]={0,0,0,0}, Q[4]={0,0,0,0}, R[4]={0,0,0,0}, S[4]={0,0,0,0};
    const u64* x0 = &sXx[(bq     ) * 64]; const u64* n0 = &sXn[(bq     ) * 64];
    const u64* x1 = &sXx[(bq +  4) * 64]; const u64* n1 = &sXn[(bq +  4) * 64];
    const u64* x2 = &sXx[(bq +  8) * 64]; const u64* n2 = &sXn[(bq +  8) * 64];
    const u64* x3 = &sXx[(bq + 12) * 64]; const u64* n3 = &sXn[(bq + 12) * 64];
#pragma unroll 4
    for (int i = 0; i < CI; ++i) {
        u64 wrp = *(const u64*)&sWr[i * 64 + 2 * op];
        u64 wip = *(const u64*)&sWi[i * 64 + 2 * op];
        P[0]=fma2(x0[i],wrp,P[0]); Q[0]=fma2(n0[i],wip,Q[0]);
        R[0]=fma2(x0[i],wip,R[0]); S[0]=fma2(n0[i],wrp,S[0]);
        P[1]=fma2(x1[i],wrp,P[1]); Q[1]=fma2(n1[i],wip,Q[1]);
        R[1]=fma2(x1[i],wip,R[1]); S[1]=fma2(n1[i],wrp,S[1]);
        P[2]=fma2(x2[i],wrp,P[2]); Q[2]=fma2(n2[i],wip,Q[2]);
        R[2]=fma2(x2[i],wip,R[2]); S[2]=fma2(n2[i],wrp,S[2]);
        P[3]=fma2(x3[i],wrp,P[3]); Q[3]=fma2(n3[i],wip,Q[3]);
        R[3]=fma2(x3[i],wip,R[3]); S[3]=fma2(n3[i],wrp,S[3]);
    }
#pragma unroll
    for (int j = 0; j < 4; ++j) {
        int b = bq + 4 * j;
        size_t base = ((size_t)(b * MD + kx) * MD + ky) * CO + 2 * op;
        *(u64*)&g_Ox[base] = add2(P[j], Q[j]);            // re = P + Q
        *(u64*)&g_Oy[base] = add2(R[j], S[j] ^ SGN2);     // im = R - S
    }
}

// ============ stage D: G[b][h][kx][o] = sum_ky O e^{+i ky h th} (SoA) ============
__global__ void __launch_bounds__(256) stageD() {
    __shared__ __align__(16) float sOx[MD * CO];   // 4 KB
    __shared__ __align__(16) float sOy[MD * CO];   // 4 KB
    __shared__ __align__(16) u64 sTc2[MD * 64];    // 8 KB  [ky][hloc]
    __shared__ __align__(16) u64 sTs2[MD * 64];    // 8 KB
    int half = blockIdx.x & 1;
    int kx   = (blockIdx.x >> 1) & 15;
    int b    = blockIdx.x >> 5;
    int hb   = half * 64;
    int tid  = threadIdx.x;
    for (int l = tid; l < 1024; l += 256) {
        int ky = l >> 6, hloc = l & 63;
        sTc2[l] = g_Tcc[ky * 128 + hb + hloc];
        sTs2[l] = g_Tss[ky * 128 + hb + hloc];
    }
    const float* Osx = g_Ox + (size_t)(b * MD + kx) * MD * CO;
    const float* Osy = g_Oy + (size_t)(b * MD + kx) * MD * CO;
    for (int l = tid; l < 256; l += 256) {
        ((float4*)sOx)[l] = ((const float4*)Osx)[l];
        ((float4*)sOy)[l] = ((const float4*)Osy)[l];
    }
    __syncthreads();

    int op = tid & 31, hl = tid >> 5;
    u64 re[8] = {0,0,0,0,0,0,0,0};
    u64 im[8] = {0,0,0,0,0,0,0,0};
#pragma unroll
    for (int ky = 0; ky < MD; ++ky) {
        u64 vx = *(const u64*)&sOx[ky * 64 + op * 2];
        u64 vy = *(const u64*)&sOy[ky * 64 + op * 2];
        u64 vyn = vy ^ SGN2;
#pragma unroll
        for (int jj = 0; jj < 8; ++jj) {
            int hloc = hl * 8 + jj;
            u64 cc = sTc2[ky * 64 + hloc];
            u64 ss = sTs2[ky * 64 + hloc];
            re[jj] = fma2(vx,  cc, re[jj]);  re[jj] = fma2(vyn, ss, re[jj]);
            im[jj] = fma2(vx,  ss, im[jj]);  im[jj] = fma2(vy,  cc, im[jj]);
        }
    }
#pragma unroll
    for (int jj = 0; jj < 8; ++jj) {
        int h = hb + hl * 8 + jj;
        size_t base = ((size_t)(b * Hh + h) * MD + kx) * CO + op * 2;
        *(u64*)&g_Gx[base] = re[jj];
        *(u64*)&g_Gy[base] = im[jj];
    }
}

// ============ stage E: y = S*Gx(0) + sum_{kx>=1} 2S(Gx c - Gy s) ============
#define YPAD 66
__global__ void __launch_bounds__(128) stageE(float* __restrict__ y) {
    __shared__ __align__(16) float sGx[MD * CO];    // 4 KB
    __shared__ __align__(16) float sGy[MD * CO];    // 4 KB
    __shared__ __align__(16) float sY [Ww * YPAD];  // 33.8 KB
    int b = blockIdx.x >> 7, h = blockIdx.x & 127;
    int tid = threadIdx.x;                           // = w
    const float4* Gxs = (const float4*)&g_Gx[(size_t)(b * Hh + h) * MD * CO];
    const float4* Gys = (const float4*)&g_Gy[(size_t)(b * Hh + h) * MD * CO];
    for (int l = tid; l < MD * CO / 4; l += 128) {
        ((float4*)sGx)[l] = Gxs[l];
        ((float4*)sGy)[l] = Gys[l];
    }
    int w = tid;
    u64 tc[16], ts[16];
#pragma unroll
    for (int kx = 0; kx < MD; ++kx) {
        tc[kx] = g_TEc[kx * 128 + w];
        ts[kx] = g_TEs[kx * 128 + w];
    }
    __syncthreads();

#pragma unroll 2
    for (int oq = 0; oq < 16; ++oq) {
        u64 a01 = 0, a23 = 0;
#pragma unroll
        for (int kx = 0; kx < MD; ++kx) {
            ulonglong2 vx = *(const ulonglong2*)&sGx[kx * 64 + oq * 4];
            ulonglong2 vy = *(const ulonglong2*)&sGy[kx * 64 + oq * 4];
            a01 = fma2(vx.x, tc[kx], a01);  a01 = fma2(vy.x, ts[kx], a01);
            a23 = fma2(vx.y, tc[kx], a23);  a23 = fma2(vy.y, ts[kx], a23);
        }
        *(u64*)&sY[w * YPAD + oq * 4    ] = a01;
        *(u64*)&sY[w * YPAD + oq * 4 + 2] = a23;
    }
    __syncthreads();
    float* yb = y + (size_t)(b * Hh + h) * Ww * CO;
    for (int l = tid; l < Ww * CO / 2; l += 128) {
        int idx = l * 2;
        int ww = idx >> 6, o = idx & 63;
        *(u64*)&yb[idx] = *(const u64*)&sY[ww * YPAD + o];
    }
}

extern "C" void kernel_launch(void* const* d_in, const int* in_sizes, int n_in,
                              void* d_out, int out_size) {
    const float* x  = (const float*)d_in[0];
    const float* wr = (const float*)d_in[1];
    const float* wi = (const float*)d_in[2];
    float* y = (float*)d_out;

    stageT<<<1032, 256>>>(wr, wi);
    stageA<<<B * 32, 128>>>(x);       // 512 blocks, 4 h-rows each
    stageB<<<B * MD, 256>>>();
    stageC<<<MD * MD, 128>>>();
    stageD<<<B * MD * 2, 256>>>();
    stageE<<<B * Hh, 128>>>(y);
}

// round 7
// speedup vs baseline: 1.5424x; 1.0835x over previous
#include <cuda_runtime.h>
#include <math.h>

#define B   16
#define Hh  128
#define Ww  128
#define CI  64
#define CO  64
#define MD  16
#define THETA 0.04908738521234052f   // 2*pi/128

typedef unsigned long long u64;

__device__ __forceinline__ u64 pk(float lo, float hi) {
    u64 r; asm("mov.b64 %0, {%1,%2};" : "=l"(r) : "f"(lo), "f"(hi)); return r;
}
__device__ __forceinline__ u64 fma2(u64 a, u64 b, u64 c) {
    u64 d; asm("fma.rn.f32x2 %0, %1, %2, %3;" : "=l"(d) : "l"(a), "l"(b), "l"(c)); return d;
}
__device__ __forceinline__ u64 add2(u64 a, u64 b) {
    u64 d; asm("add.rn.f32x2 %0, %1, %2;" : "=l"(d) : "l"(a), "l"(b)); return d;
}
#define SGN2 0x8000000080000000ULL

// ---- scratch (device globals; allocation-free). 16B aligned ----
static __device__ __align__(16) float g_Ax[B*MD*Hh*CI];     // [b][kx][h][i]  8 MB
static __device__ __align__(16) float g_Ay[B*MD*Hh*CI];     //                8 MB
static __device__ __align__(16) float g_Xx[MD*MD*B*CI];     // [m][b][i]      1 MB
static __device__ __align__(16) float g_Xy[MD*MD*B*CI];     //                1 MB
static __device__ __align__(16) float g_Wr[MD*MD*CI*CO];    // [m][i*64+o]    4 MB
static __device__ __align__(16) float g_Wi[MD*MD*CI*CO];    //                4 MB
static __device__ __align__(16) float g_Ox[B*MD*MD*CO];     // [b][kx][ky][o] 1 MB
static __device__ __align__(16) float g_Oy[B*MD*MD*CO];     //                1 MB
static __device__ __align__(16) float g_Gx[B*Hh*MD*CO];     // [b][h][kx][o]  8 MB
static __device__ __align__(16) float g_Gy[B*Hh*MD*CO];     //                8 MB

// ============ fused stage A + weight transpose ============
// blocks [0,512): A, 4 h rows each.  blocks [512,1536): weight transpose tiles.
__global__ void __launch_bounds__(128) fusedAT(const float* __restrict__ x,
                                               const float* __restrict__ wr,
                                               const float* __restrict__ wi) {
    __shared__ __align__(16) float pool[4 * 32 * 64];   // 32 KB (A data / Tw tiles)
    __shared__ __align__(16) u64 sbc[128];              // base (c,c)
    __shared__ __align__(16) u64 sbs[128];              // base (s,s)
    int tid = threadIdx.x;

    if (blockIdx.x >= 512) {
        // ---- weight transpose tile: 32 m x 32 io ----
        int t   = blockIdx.x - 512;         // 0..1023
        int bm  = t & 7;
        int bio = t >> 3;
        int tx  = tid & 31;
        int ty  = tid >> 5;                 // 0..3
        #define SR(a_, b_) pool[(a_) * 33 + (b_)]
        #define SI(a_, b_) pool[1056 + (a_) * 33 + (b_)]
#pragma unroll
        for (int r = 0; r < 8; ++r) {
            int iol = ty + r * 4;
            size_t g = (size_t)(bio * 32 + iol) * 256 + bm * 32 + tx;
            SR(iol, tx) = wr[g];
            SI(iol, tx) = wi[g];
        }
        __syncthreads();
#pragma unroll
        for (int r = 0; r < 8; ++r) {
            int ml = ty + r * 4;
            size_t dst = (size_t)(bm * 32 + ml) * 4096 + bio * 32 + tx;
            g_Wr[dst] = SR(tx, ml);
            g_Wi[dst] = SI(tx, ml);
        }
        return;
    }

    // ---- stage A: A[b][kx][h][i] = sum_w x e^{-i kx w th} ----
    {
        float s, c;
        sincosf((float)tid * THETA, &s, &c);   // tid = 0..127 = phase
        sbc[tid] = pk(c, c);
        sbs[tid] = pk(s, s);
    }
    int b  = blockIdx.x >> 5;
    int hq = blockIdx.x & 31;
    int h0 = hq * 4;
    int ip = tid & 31, kq = tid >> 5;   // kx = kq + 4q
    int i0 = 2 * ip;
    int kxs0 = kq, kxs1 = kq + 4, kxs2 = kq + 8, kxs3 = kq + 12;
    u64 re[4][4], im[4][4];
#pragma unroll
    for (int r = 0; r < 4; ++r)
#pragma unroll
        for (int q = 0; q < 4; ++q) { re[r][q] = 0; im[r][q] = 0; }

    for (int wc = 0; wc < 4; ++wc) {
        __syncthreads();
#pragma unroll
        for (int r = 0; r < 4; ++r) {
            const float4* src = (const float4*)(x + ((size_t)(b * Hh + h0 + r) * Ww + wc * 32) * CI);
            float4* dst = (float4*)&pool[r * 2048];
            for (int l = tid; l < 512; l += 128) dst[l] = src[l];
        }
        __syncthreads();
        int w0 = wc * 32;
        int id0 = (kxs0 * w0) & 127, id1 = (kxs1 * w0) & 127;
        int id2 = (kxs2 * w0) & 127, id3 = (kxs3 * w0) & 127;
#pragma unroll 4
        for (int wl = 0; wl < 32; ++wl) {
            u64 v0 = *(const u64*)&pool[0 * 2048 + wl * 64 + i0];
            u64 v1 = *(const u64*)&pool[1 * 2048 + wl * 64 + i0];
            u64 v2 = *(const u64*)&pool[2 * 2048 + wl * 64 + i0];
            u64 v3 = *(const u64*)&pool[3 * 2048 + wl * 64 + i0];
            u64 cc, ss;
            cc = sbc[id0]; ss = sbs[id0]; id0 = (id0 + kxs0) & 127;
            re[0][0]=fma2(v0,cc,re[0][0]); im[0][0]=fma2(v0,ss,im[0][0]);
            re[1][0]=fma2(v1,cc,re[1][0]); im[1][0]=fma2(v1,ss,im[1][0]);
            re[2][0]=fma2(v2,cc,re[2][0]); im[2][0]=fma2(v2,ss,im[2][0]);
            re[3][0]=fma2(v3,cc,re[3][0]); im[3][0]=fma2(v3,ss,im[3][0]);
            cc = sbc[id1]; ss = sbs[id1]; id1 = (id1 + kxs1) & 127;
            re[0][1]=fma2(v0,cc,re[0][1]); im[0][1]=fma2(v0,ss,im[0][1]);
            re[1][1]=fma2(v1,cc,re[1][1]); im[1][1]=fma2(v1,ss,im[1][1]);
            re[2][1]=fma2(v2,cc,re[2][1]); im[2][1]=fma2(v2,ss,im[2][1]);
            re[3][1]=fma2(v3,cc,re[3][1]); im[3][1]=fma2(v3,ss,im[3][1]);
            cc = sbc[id2]; ss = sbs[id2]; id2 = (id2 + kxs2) & 127;
            re[0][2]=fma2(v0,cc,re[0][2]); im[0][2]=fma2(v0,ss,im[0][2]);
            re[1][2]=fma2(v1,cc,re[1][2]); im[1][2]=fma2(v1,ss,im[1][2]);
            re[2][2]=fma2(v2,cc,re[2][2]); im[2][2]=fma2(v2,ss,im[2][2]);
            re[3][2]=fma2(v3,cc,re[3][2]); im[3][2]=fma2(v3,ss,im[3][2]);
            cc = sbc[id3]; ss = sbs[id3]; id3 = (id3 + kxs3) & 127;
            re[0][3]=fma2(v0,cc,re[0][3]); im[0][3]=fma2(v0,ss,im[0][3]);
            re[1][3]=fma2(v1,cc,re[1][3]); im[1][3]=fma2(v1,ss,im[1][3]);
            re[2][3]=fma2(v2,cc,re[2][3]); im[2][3]=fma2(v2,ss,im[2][3]);
            re[3][3]=fma2(v3,cc,re[3][3]); im[3][3]=fma2(v3,ss,im[3][3]);
        }
    }
#pragma unroll
    for (int q = 0; q < 4; ++q) {
        int kx = kq + 4 * q;
#pragma unroll
        for (int r = 0; r < 4; ++r) {
            size_t base = ((size_t)(b * MD + kx) * Hh + (h0 + r)) * CI;
            *(u64*)&g_Ax[base + i0] = re[r][q];
            *(u64*)&g_Ay[base + i0] = im[r][q] ^ SGN2;   // im = -sum v*s
        }
    }
}

// ============ stage B: X[m][b][i] = sum_h A e^{-i ky h th}  (i-chunk split) ============
__global__ void __launch_bounds__(256) stageB() {
    __shared__ __align__(16) float sBx[64 * 32];   // 8 KB (64 h x 32 i)
    __shared__ __align__(16) float sBy[64 * 32];   // 8 KB
    __shared__ __align__(16) u64 sbc[128];
    __shared__ __align__(16) u64 sbs[128];
    int b  = blockIdx.x >> 5;
    int kx = (blockIdx.x >> 1) & 15;
    int ic = blockIdx.x & 1;
    int tid = threadIdx.x;
    if (tid < 128) {
        float s, c;
        sincosf((float)tid * THETA, &s, &c);
        sbc[tid] = pk(c, c);
        sbs[tid] = pk(s, s);
    }
    int ipl = tid & 15, ky = tid >> 4;
    int i0 = 2 * ipl;
    u64 P = 0, Q = 0, R = 0, S = 0;
    const float* Abx = g_Ax + (size_t)(b * MD + kx) * Hh * CI;
    const float* Aby = g_Ay + (size_t)(b * MD + kx) * Hh * CI;
    for (int hc = 0; hc < 2; ++hc) {
        __syncthreads();
        for (int l = tid; l < 512; l += 256) {
            int row = l >> 3, q = l & 7;
            int gidx = (hc * 64 + row) * 16 + ic * 8 + q;   // float4 units
            ((float4*)sBx)[l] = ((const float4*)Abx)[gidx];
            ((float4*)sBy)[l] = ((const float4*)Aby)[gidx];
        }
        __syncthreads();
        int idx = (ky * hc * 64) & 127;
#pragma unroll 4
        for (int hl = 0; hl < 64; ++hl) {
            u64 cc = sbc[idx], ss = sbs[idx];
            idx = (idx + ky) & 127;
            u64 ar = *(const u64*)&sBx[hl * 32 + i0];
            u64 ai = *(const u64*)&sBy[hl * 32 + i0];
            P = fma2(ar, cc, P);  Q = fma2(ai, ss, Q);
            R = fma2(ai, cc, R);  S = fma2(ar, ss, S);
        }
    }
    // re = P + Q ; im = R - S
    size_t base = ((size_t)(ky * MD + kx) * B + b) * CI + ic * 32;
    *(u64*)&g_Xx[base + i0] = add2(P, Q);
    *(u64*)&g_Xy[base + i0] = add2(R, S ^ SGN2);
}

// ============ stage C: O[b][kx][ky][o] = sum_i X[m][b][i]*W[m][i][o] ============
__global__ void __launch_bounds__(256) stageC() {
    __shared__ __align__(16) float sWr[CI * CO];   // 16 KB
    __shared__ __align__(16) float sWi[CI * CO];   // 16 KB
    __shared__ __align__(16) u64 sXx[B * CI];      // 8 KB ( x, x)
    __shared__ __align__(16) u64 sXn[B * CI];      // 8 KB (-y,-y)
    int m = blockIdx.x;
    int kx = m & 15, ky = m >> 4;
    int tid = threadIdx.x;
    const float4* Wr4 = (const float4*)(g_Wr + (size_t)m * 4096);
    const float4* Wi4 = (const float4*)(g_Wi + (size_t)m * 4096);
    for (int l = tid; l < 1024; l += 256) {
        ((float4*)sWr)[l] = Wr4[l];
        ((float4*)sWi)[l] = Wi4[l];
    }
    for (int l = tid; l < 1024; l += 256) {
        float vx = g_Xx[m * 1024 + l];
        float vy = g_Xy[m * 1024 + l];
        sXx[l] = pk(vx, vx);
        sXn[l] = pk(-vy, -vy);
    }
    __syncthreads();
    int op = tid & 31, bq = tid >> 5;   // b = bq and bq+8
    u64 P0=0,Q0=0,R0=0,S0=0, P1=0,Q1=0,R1=0,S1=0;
    const u64* x0 = &sXx[(bq    ) * 64]; const u64* n0 = &sXn[(bq    ) * 64];
    const u64* x1 = &sXx[(bq + 8) * 64]; const u64* n1 = &sXn[(bq + 8) * 64];
#pragma unroll 8
    for (int i = 0; i < CI; ++i) {
        u64 wrp = *(const u64*)&sWr[i * 64 + 2 * op];
        u64 wip = *(const u64*)&sWi[i * 64 + 2 * op];
        P0=fma2(x0[i],wrp,P0); Q0=fma2(n0[i],wip,Q0);
        R0=fma2(x0[i],wip,R0); S0=fma2(n0[i],wrp,S0);
        P1=fma2(x1[i],wrp,P1); Q1=fma2(n1[i],wip,Q1);
        R1=fma2(x1[i],wip,R1); S1=fma2(n1[i],wrp,S1);
    }
    size_t base0 = ((size_t)((bq    ) * MD + kx) * MD + ky) * CO + 2 * op;
    size_t base1 = ((size_t)((bq + 8) * MD + kx) * MD + ky) * CO + 2 * op;
    *(u64*)&g_Ox[base0] = add2(P0, Q0);            // re = P + Q
    *(u64*)&g_Oy[base0] = add2(R0, S0 ^ SGN2);     // im = R - S
    *(u64*)&g_Ox[base1] = add2(P1, Q1);
    *(u64*)&g_Oy[base1] = add2(R1, S1 ^ SGN2);
}

// ============ stage D: G[b][h][kx][o] = sum_ky O e^{+i ky h th} (SoA) ============
__global__ void __launch_bounds__(256) stageD() {
    __shared__ __align__(16) float sOx[MD * CO];   // 4 KB
    __shared__ __align__(16) float sOy[MD * CO];   // 4 KB
    __shared__ __align__(16) u64 sTc2[MD * 64];    // 8 KB  [ky][hloc]
    __shared__ __align__(16) u64 sTs2[MD * 64];    // 8 KB
    int half = blockIdx.x & 1;
    int kx   = (blockIdx.x >> 1) & 15;
    int b    = blockIdx.x >> 5;
    int hb   = half * 64;
    int tid  = threadIdx.x;
    for (int l = tid; l < 1024; l += 256) {
        int ky = l >> 6, hloc = l & 63;
        float s, c;
        sincosf((float)((ky * (hb + hloc)) & 127) * THETA, &s, &c);
        sTc2[l] = pk(c, c);
        sTs2[l] = pk(s, s);
    }
    const float* Osx = g_Ox + (size_t)(b * MD + kx) * MD * CO;
    const float* Osy = g_Oy + (size_t)(b * MD + kx) * MD * CO;
    for (int l = tid; l < 256; l += 256) {
        ((float4*)sOx)[l] = ((const float4*)Osx)[l];
        ((float4*)sOy)[l] = ((const float4*)Osy)[l];
    }
    __syncthreads();

    int op = tid & 31, hl = tid >> 5;
    u64 re[8] = {0,0,0,0,0,0,0,0};
    u64 im[8] = {0,0,0,0,0,0,0,0};
#pragma unroll
    for (int ky = 0; ky < MD; ++ky) {
        u64 vx = *(const u64*)&sOx[ky * 64 + op * 2];
        u64 vy = *(const u64*)&sOy[ky * 64 + op * 2];
        u64 vyn = vy ^ SGN2;
#pragma unroll
        for (int jj = 0; jj < 8; ++jj) {
            int hloc = hl * 8 + jj;
            u64 cc = sTc2[ky * 64 + hloc];
            u64 ss = sTs2[ky * 64 + hloc];
            re[jj] = fma2(vx,  cc, re[jj]);  re[jj] = fma2(vyn, ss, re[jj]);
            im[jj] = fma2(vx,  ss, im[jj]);  im[jj] = fma2(vy,  cc, im[jj]);
        }
    }
#pragma unroll
    for (int jj = 0; jj < 8; ++jj) {
        int h = hb + hl * 8 + jj;
        size_t base = ((size_t)(b * Hh + h) * MD + kx) * CO + op * 2;
        *(u64*)&g_Gx[base] = re[jj];
        *(u64*)&g_Gy[base] = im[jj];
    }
}

// ============ stage E: y = S*Gx(0) + sum_{kx>=1} 2S(Gx c - Gy s) ============
#define YPAD 66
__global__ void __launch_bounds__(128) stageE(float* __restrict__ y) {
    __shared__ __align__(16) float sGx[MD * CO];    // 4 KB
    __shared__ __align__(16) float sGy[MD * CO];    // 4 KB
    __shared__ __align__(16) float sY [Ww * YPAD];  // 33.8 KB
    __shared__ __align__(16) u64 sEc[128];          // (2Sc,2Sc)
    __shared__ __align__(16) u64 sEs[128];          // (-2Ss,-2Ss)
    int b = blockIdx.x >> 7, h = blockIdx.x & 127;
    int tid = threadIdx.x;                           // = w
    const float SC = 1.0f / 16384.0f;                // ortho fwd*inv = 1/(H*W)
    {
        float s, c;
        sincosf((float)tid * THETA, &s, &c);
        sEc[tid] = pk(2.0f * SC * c, 2.0f * SC * c);
        sEs[tid] = pk(-2.0f * SC * s, -2.0f * SC * s);
    }
    const float4* Gxs = (const float4*)&g_Gx[(size_t)(b * Hh + h) * MD * CO];
    const float4* Gys = (const float4*)&g_Gy[(size_t)(b * Hh + h) * MD * CO];
    for (int l = tid; l < MD * CO / 4; l += 128) {
        ((float4*)sGx)[l] = Gxs[l];
        ((float4*)sGy)[l] = Gys[l];
    }
    __syncthreads();
    int w = tid;
    u64 tc[16], ts[16];
    tc[0] = pk(SC, SC);  ts[0] = 0;
#pragma unroll
    for (int kx = 1; kx < MD; ++kx) {
        int idx = (kx * w) & 127;
        tc[kx] = sEc[idx];
        ts[kx] = sEs[idx];
    }

#pragma unroll 2
    for (int oq = 0; oq < 16; ++oq) {
        u64 a01 = 0, a23 = 0;
#pragma unroll
        for (int kx = 0; kx < MD; ++kx) {
            ulonglong2 vx = *(const ulonglong2*)&sGx[kx * 64 + oq * 4];
            ulonglong2 vy = *(const ulonglong2*)&sGy[kx * 64 + oq * 4];
            a01 = fma2(vx.x, tc[kx], a01);  a01 = fma2(vy.x, ts[kx], a01);
            a23 = fma2(vx.y, tc[kx], a23);  a23 = fma2(vy.y, ts[kx], a23);
        }
        *(u64*)&sY[w * YPAD + oq * 4    ] = a01;
        *(u64*)&sY[w * YPAD + oq * 4 + 2] = a23;
    }
    __syncthreads();
    float* yb = y + (size_t)(b * Hh + h) * Ww * CO;
    for (int l = tid; l < Ww * CO / 2; l += 128) {
        int idx = l * 2;
        int ww = idx >> 6, o = idx & 63;
        *(u64*)&yb[idx] = *(const u64*)&sY[ww * YPAD + o];
    }
}

extern "C" void kernel_launch(void* const* d_in, const int* in_sizes, int n_in,
                              void* d_out, int out_size) {
    const float* x  = (const float*)d_in[0];
    const float* wr = (const float*)d_in[1];
    const float* wi = (const float*)d_in[2];
    float* y = (float*)d_out;

    fusedAT<<<1536, 128>>>(x, wr, wi);   // 512 A-blocks + 1024 transpose blocks
    stageB<<<B * MD * 2, 256>>>();
    stageC<<<MD * MD, 256>>>();
    stageD<<<B * MD * 2, 256>>>();
    stageE<<<B * Hh, 128>>>(y);
}